// round 1
// baseline (speedup 1.0000x reference)
#include <cuda_runtime.h>
#include <cuda_bf16.h>
#include <math.h>

#define BB   128
#define CH   24
#define INCH 64
#define HW   32
#define PIX  1024           // 32*32
#define D    (CH*PIX)       // 24576
#define MM   5
#define EPSV 1e-5f
#define LAMV 1e-4f

#define SMEM1 (24*34*34*4)          // 110976 B
#define SMEM2 (64*18*34*4)          // 156672 B

// ---------------- device scratch (static, zero alloc at runtime) ----------------
__device__ float g_pre [BB*D];
__device__ float g_xp  [BB*D];
__device__ float g_X   [MM*BB*D];
__device__ float g_F   [MM*BB*D];
__device__ float g_t1  [BB*INCH*PIX];
__device__ float g_y   [BB*INCH*PIX];
__device__ float g_t2  [BB*D];
__device__ float g_H   [BB*MM*MM];
__device__ float g_al  [BB*MM];
__device__ float g_bmu [CH];
__device__ float g_brs [CH];
__device__ float g_pmu [CH];
__device__ float g_prs [CH];
__device__ float g_pool[BB*CH*16];

// ---------------- block reduce (sum, sumsq) ----------------
__device__ __forceinline__ void block_reduce_2(float& s, float& s2, float* shm) {
    __syncthreads();
    int lane = threadIdx.x & 31, wid = threadIdx.x >> 5;
#pragma unroll
    for (int o = 16; o > 0; o >>= 1) {
        s  += __shfl_down_sync(0xffffffffu, s,  o);
        s2 += __shfl_down_sync(0xffffffffu, s2, o);
    }
    if (lane == 0) { shm[wid] = s; shm[32 + wid] = s2; }
    __syncthreads();
    int nw = (blockDim.x + 31) >> 5;
    if (wid == 0) {
        s  = (lane < nw) ? shm[lane]      : 0.f;
        s2 = (lane < nw) ? shm[32 + lane] : 0.f;
#pragma unroll
        for (int o = 16; o > 0; o >>= 1) {
            s  += __shfl_down_sync(0xffffffffu, s,  o);
            s2 += __shfl_down_sync(0xffffffffu, s2, o);
        }
        if (lane == 0) { shm[0] = s; shm[32] = s2; }
    }
    __syncthreads();
    s = shm[0]; s2 = shm[32];
}

// ---------------- pre conv 3->24 (+bias) ----------------
__global__ void preconv_kernel(const float* __restrict__ x, const float* __restrict__ w,
                               const float* __restrict__ bias, float* __restrict__ out) {
    __shared__ float s[3*34*34];
    int b = blockIdx.x, tid = threadIdx.x;
    for (int i = tid; i < 3*1156; i += 256) {
        int c = i / 1156, rem = i % 1156, r = rem / 34, cx = rem % 34;
        float v = 0.f;
        if (r >= 1 && r <= 32 && cx >= 1 && cx <= 32)
            v = x[((b*3 + c)*32 + (r-1))*32 + (cx-1)];
        s[i] = v;
    }
    __syncthreads();
    int py = tid >> 3, px0 = (tid & 7) << 2;
    for (int oc0 = 0; oc0 < 24; oc0 += 8) {
        float acc[8][4];
#pragma unroll
        for (int j = 0; j < 8; j++) {
            float bv = __ldg(&bias[oc0 + j]);
#pragma unroll
            for (int p = 0; p < 4; p++) acc[j][p] = bv;
        }
        for (int ic = 0; ic < 3; ic++)
            for (int ky = 0; ky < 3; ky++) {
                const float* row = &s[ic*1156 + (py + ky)*34 + px0];
                float r0=row[0],r1=row[1],r2=row[2],r3=row[3],r4=row[4],r5=row[5];
#pragma unroll
                for (int j = 0; j < 8; j++) {
                    int oc = oc0 + j;
                    const float* wq = &w[((oc*3 + ic)*3 + ky)*3];
                    float w0=__ldg(wq), w1=__ldg(wq+1), w2=__ldg(wq+2);
                    acc[j][0] += r0*w0 + r1*w1 + r2*w2;
                    acc[j][1] += r1*w0 + r2*w1 + r3*w2;
                    acc[j][2] += r2*w0 + r3*w1 + r4*w2;
                    acc[j][3] += r3*w0 + r4*w1 + r5*w2;
                }
            }
#pragma unroll
        for (int j = 0; j < 8; j++)
#pragma unroll
            for (int p = 0; p < 4; p++)
                out[(b*24 + oc0 + j)*PIX + py*32 + px0 + p] = acc[j][p];
    }
}

// ---------------- batchnorm stats (per channel over N,H,W; optional relu) ----------------
__global__ void bn_stats_kernel(const float* __restrict__ in, float* __restrict__ mu,
                                float* __restrict__ rstd, int relu_flag) {
    __shared__ float shm[64];
    int c = blockIdx.x;
    float s = 0.f, s2 = 0.f;
    for (int i = threadIdx.x; i < BB*PIX; i += blockDim.x) {
        int b = i >> 10, p = i & 1023;
        float v = in[(b*CH + c)*PIX + p];
        if (relu_flag) v = fmaxf(v, 0.f);
        s += v; s2 += v*v;
    }
    block_reduce_2(s, s2, shm);
    if (threadIdx.x == 0) {
        float m = s / (float)(BB*PIX);
        float var = s2 / (float)(BB*PIX) - m*m;
        mu[c] = m;
        rstd[c] = rsqrtf(var + EPSV);
    }
}

__global__ void bn_apply_kernel(const float* __restrict__ in, const float* __restrict__ mu,
                                const float* __restrict__ rstd, const float* __restrict__ g,
                                const float* __restrict__ bta, float* __restrict__ out) {
    int idx = blockIdx.x*256 + threadIdx.x;
    if (idx >= BB*D) return;
    int c = (idx >> 10) % CH;
    out[idx] = (in[idx] - mu[c]) * rstd[c] * g[c] + bta[c];
}

// ---------------- conv1: 24->64, 3x3 SAME, relu ----------------
__global__ void conv1_kernel(const float* __restrict__ z, const float* __restrict__ w,
                             float* __restrict__ out) {
    extern __shared__ float s[];           // 24*1156 floats
    int b = blockIdx.x, tid = threadIdx.x;
    for (int i = tid; i < 24*1156; i += 256) {
        int c = i / 1156, rem = i % 1156, r = rem / 34, cx = rem % 34;
        float v = 0.f;
        if (r >= 1 && r <= 32 && cx >= 1 && cx <= 32)
            v = z[(b*24 + c)*PIX + (r-1)*32 + (cx-1)];
        s[i] = v;
    }
    __syncthreads();
    int py = tid >> 3, px0 = (tid & 7) << 2;
    for (int oc0 = 0; oc0 < 64; oc0 += 16) {
        float acc[16][4];
#pragma unroll
        for (int j = 0; j < 16; j++)
#pragma unroll
            for (int p = 0; p < 4; p++) acc[j][p] = 0.f;
        for (int ic = 0; ic < 24; ic++)
            for (int ky = 0; ky < 3; ky++) {
                const float* row = &s[ic*1156 + (py + ky)*34 + px0];
                float r0=row[0],r1=row[1],r2=row[2],r3=row[3],r4=row[4],r5=row[5];
#pragma unroll
                for (int j = 0; j < 16; j++) {
                    int oc = oc0 + j;
                    const float* wq = &w[((oc*24 + ic)*3 + ky)*3];
                    float w0=__ldg(wq), w1=__ldg(wq+1), w2=__ldg(wq+2);
                    acc[j][0] += r0*w0 + r1*w1 + r2*w2;
                    acc[j][1] += r1*w0 + r2*w1 + r3*w2;
                    acc[j][2] += r2*w0 + r3*w1 + r4*w2;
                    acc[j][3] += r3*w0 + r4*w1 + r5*w2;
                }
            }
#pragma unroll
        for (int j = 0; j < 16; j++)
#pragma unroll
            for (int p = 0; p < 4; p++)
                out[(b*64 + oc0 + j)*PIX + py*32 + px0 + p] = fmaxf(acc[j][p], 0.f);
    }
}

// ---------------- gn1: groupnorm over 8 groups of 8 channels (INNER=64) ----------------
__global__ void gn1_kernel(const float* __restrict__ in, const float* __restrict__ g,
                           const float* __restrict__ bta, float* __restrict__ out) {
    __shared__ float buf[8192];
    __shared__ float shm[64];
    int b = blockIdx.x >> 3, grp = blockIdx.x & 7;
    int base = (b*64 + grp*8)*PIX;
    float s = 0.f, s2 = 0.f;
    for (int i = threadIdx.x; i < 8192; i += 256) {
        float v = in[base + i];
        buf[i] = v; s += v; s2 += v*v;
    }
    block_reduce_2(s, s2, shm);
    float m = s / 8192.f;
    float rs = rsqrtf(s2 / 8192.f - m*m + EPSV);
    for (int i = threadIdx.x; i < 8192; i += 256) {
        int c = grp*8 + (i >> 10);
        out[base + i] = (buf[i] - m) * rs * g[c] + bta[c];
    }
}

// ---------------- conv2: 64->24, 3x3 SAME, + xp (residual input) ----------------
__global__ void conv2_kernel(const float* __restrict__ y, const float* __restrict__ w,
                             const float* __restrict__ xp, float* __restrict__ out) {
    extern __shared__ float s[];           // 64*18*34 floats
    int b = blockIdx.x, half = blockIdx.y, tid = threadIdx.x;
    int row0 = half * 16;
    for (int i = tid; i < 64*612; i += 256) {
        int c = i / 612, rem = i % 612, r = rem / 34, cx = rem % 34;
        int gr = row0 + r - 1, gc = cx - 1;
        float v = 0.f;
        if (gr >= 0 && gr < 32 && gc >= 0 && gc < 32)
            v = y[(b*64 + c)*PIX + gr*32 + gc];
        s[i] = v;
    }
    __syncthreads();
    int grpi = tid & 127, och = tid >> 7;        // och in {0,1}
    int py = grpi >> 3, px0 = (grpi & 7) << 2;   // py 0..15
    float acc[12][4];
#pragma unroll
    for (int j = 0; j < 12; j++)
#pragma unroll
        for (int p = 0; p < 4; p++) acc[j][p] = 0.f;
    for (int ic = 0; ic < 64; ic++)
        for (int ky = 0; ky < 3; ky++) {
            const float* row = &s[ic*612 + (py + ky)*34 + px0];
            float r0=row[0],r1=row[1],r2=row[2],r3=row[3],r4=row[4],r5=row[5];
#pragma unroll
            for (int j = 0; j < 12; j++) {
                int oc = och*12 + j;
                const float* wq = &w[((oc*64 + ic)*3 + ky)*3];
                float w0=__ldg(wq), w1=__ldg(wq+1), w2=__ldg(wq+2);
                acc[j][0] += r0*w0 + r1*w1 + r2*w2;
                acc[j][1] += r1*w0 + r2*w1 + r3*w2;
                acc[j][2] += r2*w0 + r3*w1 + r4*w2;
                acc[j][3] += r3*w0 + r4*w1 + r5*w2;
            }
        }
    int gy = row0 + py;
#pragma unroll
    for (int j = 0; j < 12; j++)
#pragma unroll
        for (int p = 0; p < 4; p++) {
            int idx = (b*24 + och*12 + j)*PIX + gy*32 + px0 + p;
            out[idx] = xp[idx] + acc[j][p];
        }
}

// ---------------- fused gn2 -> +z -> relu -> gn3 (groups of 3 channels) ----------------
__global__ void gn23_kernel(const float* __restrict__ t2, const float* __restrict__ z,
                            const float* __restrict__ g2, const float* __restrict__ b2,
                            const float* __restrict__ g3, const float* __restrict__ b3,
                            float* __restrict__ out) {
    __shared__ float buf[3072];
    __shared__ float shm[64];
    int b = blockIdx.x >> 3, grp = blockIdx.x & 7;
    int base = (b*24 + grp*3)*PIX;
    float s = 0.f, s2 = 0.f;
    for (int i = threadIdx.x; i < 3072; i += 256) {
        float v = t2[base + i];
        buf[i] = v; s += v; s2 += v*v;
    }
    block_reduce_2(s, s2, shm);
    float m1 = s / 3072.f;
    float rs1 = rsqrtf(s2 / 3072.f - m1*m1 + EPSV);
    float s3 = 0.f, s4 = 0.f;
    for (int i = threadIdx.x; i < 3072; i += 256) {
        int c = grp*3 + (i >> 10);
        float u = (buf[i] - m1) * rs1 * g2[c] + b2[c];
        float v = fmaxf(z[base + i] + u, 0.f);
        buf[i] = v; s3 += v; s4 += v*v;
    }
    block_reduce_2(s3, s4, shm);
    float m2 = s3 / 3072.f;
    float rs2 = rsqrtf(s4 / 3072.f - m2*m2 + EPSV);
    for (int i = threadIdx.x; i < 3072; i += 256) {
        int c = grp*3 + (i >> 10);
        out[base + i] = (buf[i] - m2) * rs2 * g3[c] + b3[c];
    }
}

// ---------------- Anderson: Gram matrix H_in[b][i][j] = <G_i, G_j> ----------------
__global__ void hdot_kernel(int n, const float* __restrict__ Fb, const float* __restrict__ Xb,
                            float* __restrict__ H) {
    int b = blockIdx.x, tid = threadIdx.x;
    float acc[15];
#pragma unroll
    for (int i = 0; i < 15; i++) acc[i] = 0.f;
    size_t bd = (size_t)b * D;
    for (int d = tid; d < D; d += 256) {
        float gg[5];
#pragma unroll
        for (int i = 0; i < 5; i++) {
            size_t off = (size_t)i * (BB*(size_t)D) + bd + d;
            gg[i] = (i < n) ? (Fb[off] - Xb[off]) : 0.f;
        }
        int idx = 0;
#pragma unroll
        for (int i = 0; i < 5; i++)
#pragma unroll
            for (int j = i; j < 5; j++) { acc[idx] += gg[i]*gg[j]; idx++; }
    }
    __shared__ float sh[8][15];
    int lane = tid & 31, wid = tid >> 5;
#pragma unroll
    for (int p = 0; p < 15; p++) {
        float v = acc[p];
#pragma unroll
        for (int o = 16; o > 0; o >>= 1) v += __shfl_down_sync(0xffffffffu, v, o);
        if (lane == 0) sh[wid][p] = v;
    }
    __syncthreads();
    if (tid < 15) {
        float v = 0.f;
#pragma unroll
        for (int wq = 0; wq < 8; wq++) v += sh[wq][tid];
        int rem = tid, ii = 0;
        while (rem >= 5 - ii) { rem -= (5 - ii); ii++; }
        int jj = ii + rem;
        H[b*25 + ii*5 + jj] = v;
        H[b*25 + jj*5 + ii] = v;
    }
}

// ---------------- Anderson: tiny (n+1)x(n+1) solve per batch ----------------
__global__ void solve_kernel(int n, const float* __restrict__ H, float* __restrict__ alpha) {
    int b = blockIdx.x * blockDim.x + threadIdx.x;
    if (b >= BB) return;
    int m = n + 1;
    float A[6][7];
    for (int i = 0; i < m; i++)
        for (int j = 0; j <= m; j++) A[i][j] = 0.f;
    for (int j = 1; j < m; j++) { A[0][j] = 1.f; A[j][0] = 1.f; }
    for (int i = 0; i < n; i++)
        for (int j = 0; j < n; j++)
            A[i+1][j+1] = H[b*25 + i*5 + j] + ((i == j) ? LAMV : 0.f);
    A[0][m] = 1.f;
    for (int col = 0; col < m; col++) {
        int piv = col; float best = fabsf(A[col][col]);
        for (int r = col + 1; r < m; r++) {
            float v = fabsf(A[r][col]);
            if (v > best) { best = v; piv = r; }
        }
        if (piv != col)
            for (int j = col; j <= m; j++) { float t = A[col][j]; A[col][j] = A[piv][j]; A[piv][j] = t; }
        float inv = 1.f / A[col][col];
        for (int r = col + 1; r < m; r++) {
            float f = A[r][col] * inv;
            for (int j = col; j <= m; j++) A[r][j] -= f * A[col][j];
        }
    }
    float xs[6];
    for (int i = m - 1; i >= 0; i--) {
        float v = A[i][m];
        for (int j = i + 1; j < m; j++) v -= A[i][j] * xs[j];
        xs[i] = v / A[i][i];
    }
    for (int i = 0; i < 5; i++) alpha[b*5 + i] = (i < n) ? xs[i + 1] : 0.f;
}

// ---------------- Anderson: xnew = sum alpha_i * F_i (BETA = 1) ----------------
__global__ void xnew_kernel(int n, const float* __restrict__ Fb, const float* __restrict__ alpha,
                            float* __restrict__ Xslot) {
    int idx = blockIdx.x*256 + threadIdx.x;
    if (idx >= BB*D) return;
    int b = idx / D;
    float acc = 0.f;
#pragma unroll
    for (int i = 0; i < 5; i++)
        if (i < n) acc += alpha[b*5 + i] * Fb[(size_t)i * (BB*(size_t)D) + idx];
    Xslot[idx] = acc;
}

// ---------------- post: relu -> BN apply -> 8x8 avgpool ----------------
__global__ void pool_kernel(const float* __restrict__ z, const float* __restrict__ mu,
                            const float* __restrict__ rstd, const float* __restrict__ g,
                            const float* __restrict__ bta, float* __restrict__ pooled) {
    __shared__ float pl[16];
    int b = blockIdx.x / 24, c = blockIdx.x % 24;
    if (threadIdx.x < 16) pl[threadIdx.x] = 0.f;
    __syncthreads();
    float mc = mu[c], rc = rstd[c], gc = g[c], bc = bta[c];
    for (int i = threadIdx.x; i < 1024; i += 256) {
        int yy = i >> 5, xx = i & 31;
        float v = fmaxf(z[(b*24 + c)*PIX + i], 0.f);
        v = (v - mc) * rc * gc + bc;
        atomicAdd(&pl[(yy >> 3)*4 + (xx >> 3)], v);
    }
    __syncthreads();
    if (threadIdx.x < 16)
        pooled[(b*24 + c)*16 + threadIdx.x] = pl[threadIdx.x] * (1.f/64.f);
}

// ---------------- final FC: [128,384] x [10,384]^T ----------------
__global__ void fc_kernel(const float* __restrict__ pooled, const float* __restrict__ w,
                          const float* __restrict__ bias, float* __restrict__ out) {
    int b = blockIdx.x;
    int warp = threadIdx.x >> 5, lane = threadIdx.x & 31;
    float acc = 0.f;
    for (int k = lane; k < 384; k += 32)
        acc += pooled[b*384 + k] * w[warp*384 + k];
#pragma unroll
    for (int o = 16; o > 0; o >>= 1) acc += __shfl_down_sync(0xffffffffu, acc, o);
    if (lane == 0) out[b*10 + warp] = acc + bias[warp];
}

// ---------------- host orchestration ----------------
extern "C" void kernel_launch(void* const* d_in, const int* in_sizes, int n_in,
                              void* d_out, int out_size) {
    const float* x     = (const float*)d_in[0];
    const float* pw    = (const float*)d_in[1];
    const float* pbia  = (const float*)d_in[2];
    const float* pbn_g = (const float*)d_in[3];
    const float* pbn_b = (const float*)d_in[4];
    const float* w1    = (const float*)d_in[5];
    const float* g1g   = (const float*)d_in[6];
    const float* g1b   = (const float*)d_in[7];
    const float* w2    = (const float*)d_in[8];
    const float* g2g   = (const float*)d_in[9];
    const float* g2b   = (const float*)d_in[10];
    const float* g3g   = (const float*)d_in[11];
    const float* g3b   = (const float*)d_in[12];
    const float* qbn_g = (const float*)d_in[13];
    const float* qbn_b = (const float*)d_in[14];
    const float* fcw   = (const float*)d_in[15];
    const float* fcb   = (const float*)d_in[16];
    float* out = (float*)d_out;

    cudaFuncSetAttribute(conv1_kernel, cudaFuncAttributeMaxDynamicSharedMemorySize, SMEM1);
    cudaFuncSetAttribute(conv2_kernel, cudaFuncAttributeMaxDynamicSharedMemorySize, SMEM2);

    float *Xb, *Fb, *xp, *pre, *t1, *yb, *t2, *Hb, *al, *bmu, *brs, *pmu, *prs, *pl;
    cudaGetSymbolAddress((void**)&Xb,  g_X);
    cudaGetSymbolAddress((void**)&Fb,  g_F);
    cudaGetSymbolAddress((void**)&xp,  g_xp);
    cudaGetSymbolAddress((void**)&pre, g_pre);
    cudaGetSymbolAddress((void**)&t1,  g_t1);
    cudaGetSymbolAddress((void**)&yb,  g_y);
    cudaGetSymbolAddress((void**)&t2,  g_t2);
    cudaGetSymbolAddress((void**)&Hb,  g_H);
    cudaGetSymbolAddress((void**)&al,  g_al);
    cudaGetSymbolAddress((void**)&bmu, g_bmu);
    cudaGetSymbolAddress((void**)&brs, g_brs);
    cudaGetSymbolAddress((void**)&pmu, g_pmu);
    cudaGetSymbolAddress((void**)&prs, g_prs);
    cudaGetSymbolAddress((void**)&pl,  g_pool);

    const size_t SLOT = (size_t)BB * D;

    // pre: conv + BN (training stats)
    preconv_kernel<<<128, 256>>>(x, pw, pbia, pre);
    bn_stats_kernel<<<24, 512>>>(pre, bmu, brs, 0);
    bn_apply_kernel<<<(BB*D + 255)/256, 256>>>(pre, bmu, brs, pbn_g, pbn_b, xp);

    // Anderson init: x0 = 0
    cudaMemsetAsync(Xb, 0, SLOT * sizeof(float));

    auto runf = [&](const float* z, float* fo) {
        conv1_kernel<<<128, 256, SMEM1>>>(z, w1, t1);
        gn1_kernel<<<1024, 256>>>(t1, g1g, g1b, yb);
        conv2_kernel<<<dim3(128, 2), 256, SMEM2>>>(yb, w2, xp, t2);
        gn23_kernel<<<1024, 256>>>(t2, z, g2g, g2b, g3g, g3b, fo);
    };

    runf(Xb, Fb);                                                 // F0 = f(0)
    cudaMemcpyAsync(Xb + SLOT, Fb, SLOT * sizeof(float), cudaMemcpyDeviceToDevice);
    runf(Xb + SLOT, Fb + SLOT);                                   // F1 = f(F0)

    for (int k = 2; k < 25; k++) {
        int n = (k < 5) ? k : 5;
        int slt = k % 5;
        hdot_kernel<<<128, 256>>>(n, Fb, Xb, Hb);
        solve_kernel<<<1, 128>>>(n, Hb, al);
        xnew_kernel<<<(BB*D + 255)/256, 256>>>(n, Fb, al, Xb + (size_t)slt * SLOT);
        runf(Xb + (size_t)slt * SLOT, Fb + (size_t)slt * SLOT);
    }

    // z = f(z_star) = f(X[:,4]) = F[:,4]  (last iteration already computed it)
    const float* zf = Fb + 4 * SLOT;

    bn_stats_kernel<<<24, 512>>>(zf, pmu, prs, 1);
    pool_kernel<<<128*24, 256>>>(zf, pmu, prs, qbn_g, qbn_b, pl);
    fc_kernel<<<128, 320>>>(pl, fcw, fcb, out);
}

// round 2
// speedup vs baseline: 1.5610x; 1.5610x over previous
#include <cuda_runtime.h>
#include <cuda_bf16.h>
#include <math.h>

#define BB   128
#define CH   24
#define INCH 64
#define PIX  1024           // 32*32
#define D    (CH*PIX)       // 24576
#define MM   5
#define EPSV 1e-5f
#define LAMV 1e-4f

#define RS1   35                      // padded row stride (conflict-free)
#define IN1   (24*34*RS1)             // 28560 floats
#define W1SZ  (64*24*9)               // 13824 floats
#define SMEM1 ((IN1 + W1SZ)*4)        // 169536 B

#define RS2   35
#define IN2   (64*18*RS2)             // 40320 floats
#define W2SZ  (24*64*9)               // 13824 floats
#define SMEM2 ((IN2 + W2SZ)*4)        // 216576 B

// ---------------- device scratch ----------------
__device__ float g_pre [BB*D];
__device__ float g_xp  [BB*D];
__device__ float g_X   [MM*BB*D];
__device__ float g_F   [MM*BB*D];
__device__ float g_t1  [BB*INCH*PIX];
__device__ float g_y   [BB*INCH*PIX];
__device__ float g_t2  [BB*D];
__device__ float g_al  [BB*MM];
__device__ float g_bmu [CH];
__device__ float g_brs [CH];
__device__ float g_pmu [CH];
__device__ float g_prs [CH];
__device__ float g_pool[BB*CH*16];

// ---------------- block reduce (sum, sumsq) ----------------
__device__ __forceinline__ void block_reduce_2(float& s, float& s2, float* shm) {
    __syncthreads();
    int lane = threadIdx.x & 31, wid = threadIdx.x >> 5;
#pragma unroll
    for (int o = 16; o > 0; o >>= 1) {
        s  += __shfl_down_sync(0xffffffffu, s,  o);
        s2 += __shfl_down_sync(0xffffffffu, s2, o);
    }
    if (lane == 0) { shm[wid] = s; shm[32 + wid] = s2; }
    __syncthreads();
    int nw = (blockDim.x + 31) >> 5;
    if (wid == 0) {
        s  = (lane < nw) ? shm[lane]      : 0.f;
        s2 = (lane < nw) ? shm[32 + lane] : 0.f;
#pragma unroll
        for (int o = 16; o > 0; o >>= 1) {
            s  += __shfl_down_sync(0xffffffffu, s,  o);
            s2 += __shfl_down_sync(0xffffffffu, s2, o);
        }
        if (lane == 0) { shm[0] = s; shm[32] = s2; }
    }
    __syncthreads();
    s = shm[0]; s2 = shm[32];
}

// ---------------- pre conv 3->24 (+bias), one-shot ----------------
__global__ void preconv_kernel(const float* __restrict__ x, const float* __restrict__ w,
                               const float* __restrict__ bias, float* __restrict__ out) {
    __shared__ float s[3*34*34];
    int b = blockIdx.x, tid = threadIdx.x;
    for (int i = tid; i < 3*1156; i += 256) {
        int c = i / 1156, rem = i % 1156, r = rem / 34, cx = rem % 34;
        float v = 0.f;
        if (r >= 1 && r <= 32 && cx >= 1 && cx <= 32)
            v = x[((b*3 + c)*32 + (r-1))*32 + (cx-1)];
        s[i] = v;
    }
    __syncthreads();
    int py = tid >> 3, px0 = (tid & 7) << 2;
    for (int oc0 = 0; oc0 < 24; oc0 += 8) {
        float acc[8][4];
#pragma unroll
        for (int j = 0; j < 8; j++) {
            float bv = __ldg(&bias[oc0 + j]);
#pragma unroll
            for (int p = 0; p < 4; p++) acc[j][p] = bv;
        }
        for (int ic = 0; ic < 3; ic++)
#pragma unroll
            for (int ky = 0; ky < 3; ky++) {
                const float* row = &s[ic*1156 + (py + ky)*34 + px0];
                float r0=row[0],r1=row[1],r2=row[2],r3=row[3],r4=row[4],r5=row[5];
#pragma unroll
                for (int j = 0; j < 8; j++) {
                    int oc = oc0 + j;
                    const float* wq = &w[((oc*3 + ic)*3 + ky)*3];
                    float w0=__ldg(wq), w1=__ldg(wq+1), w2=__ldg(wq+2);
                    acc[j][0] += r0*w0 + r1*w1 + r2*w2;
                    acc[j][1] += r1*w0 + r2*w1 + r3*w2;
                    acc[j][2] += r2*w0 + r3*w1 + r4*w2;
                    acc[j][3] += r3*w0 + r4*w1 + r5*w2;
                }
            }
#pragma unroll
        for (int j = 0; j < 8; j++)
#pragma unroll
            for (int p = 0; p < 4; p++)
                out[(b*24 + oc0 + j)*PIX + py*32 + px0 + p] = acc[j][p];
    }
}

// ---------------- batchnorm stats ----------------
__global__ void bn_stats_kernel(const float* __restrict__ in, float* __restrict__ mu,
                                float* __restrict__ rstd, int relu_flag) {
    __shared__ float shm[64];
    int c = blockIdx.x;
    float s = 0.f, s2 = 0.f;
    for (int i = threadIdx.x; i < BB*PIX; i += blockDim.x) {
        int b = i >> 10, p = i & 1023;
        float v = in[(b*CH + c)*PIX + p];
        if (relu_flag) v = fmaxf(v, 0.f);
        s += v; s2 += v*v;
    }
    block_reduce_2(s, s2, shm);
    if (threadIdx.x == 0) {
        float m = s / (float)(BB*PIX);
        float var = s2 / (float)(BB*PIX) - m*m;
        mu[c] = m;
        rstd[c] = rsqrtf(var + EPSV);
    }
}

__global__ void bn_apply_kernel(const float* __restrict__ in, const float* __restrict__ mu,
                                const float* __restrict__ rstd, const float* __restrict__ g,
                                const float* __restrict__ bta, float* __restrict__ out) {
    int idx = blockIdx.x*256 + threadIdx.x;
    if (idx >= BB*D) return;
    int c = (idx >> 10) % CH;
    out[idx] = (in[idx] - mu[c]) * rstd[c] * g[c] + bta[c];
}

// ---------------- conv1: 24->64, 3x3 SAME, relu; weights in smem ----------------
__global__ void __launch_bounds__(512, 1)
conv1_kernel(const float* __restrict__ z, const float* __restrict__ w,
             float* __restrict__ out) {
    extern __shared__ float s[];         // [IN1] input + [W1SZ] weights
    float* ws = s + IN1;
    int b = blockIdx.x, tid = threadIdx.x;
    for (int i = tid; i < W1SZ; i += 512) ws[i] = w[i];
    for (int i = tid; i < 24*1156; i += 512) {
        int c = i / 1156, rem = i % 1156, r = rem / 34, cx = rem % 34;
        float v = 0.f;
        if (r >= 1 && r <= 32 && cx >= 1 && cx <= 32)
            v = z[(b*24 + c)*PIX + (r-1)*32 + (cx-1)];
        s[c*(34*RS1) + r*RS1 + cx] = v;
    }
    __syncthreads();
    int ocg = tid >> 8;                       // 0..1 -> oc halves
    int t = tid & 255;
    int py = t >> 3, px0 = (t & 7) << 2;
#pragma unroll
    for (int tile = 0; tile < 2; tile++) {
        int oc0 = ocg*32 + tile*16;
        float acc[16][4];
#pragma unroll
        for (int j = 0; j < 16; j++)
#pragma unroll
            for (int p = 0; p < 4; p++) acc[j][p] = 0.f;
        for (int ic = 0; ic < 24; ic++)
#pragma unroll
            for (int ky = 0; ky < 3; ky++) {
                const float* row = &s[ic*(34*RS1) + (py + ky)*RS1 + px0];
                float r0=row[0],r1=row[1],r2=row[2],r3=row[3],r4=row[4],r5=row[5];
#pragma unroll
                for (int j = 0; j < 16; j++) {
                    const float* wq = &ws[((oc0 + j)*24 + ic)*9 + ky*3];
                    float w0=wq[0], w1=wq[1], w2=wq[2];
                    acc[j][0] += r0*w0 + r1*w1 + r2*w2;
                    acc[j][1] += r1*w0 + r2*w1 + r3*w2;
                    acc[j][2] += r2*w0 + r3*w1 + r4*w2;
                    acc[j][3] += r3*w0 + r4*w1 + r5*w2;
                }
            }
#pragma unroll
        for (int j = 0; j < 16; j++)
#pragma unroll
            for (int p = 0; p < 4; p++)
                out[(b*64 + oc0 + j)*PIX + py*32 + px0 + p] = fmaxf(acc[j][p], 0.f);
    }
}

// ---------------- gn1: groups of 8 channels over INNER=64 ----------------
__global__ void gn1_kernel(const float* __restrict__ in, const float* __restrict__ g,
                           const float* __restrict__ bta, float* __restrict__ out) {
    __shared__ float buf[8192];
    __shared__ float shm[64];
    int b = blockIdx.x >> 3, grp = blockIdx.x & 7;
    int base = (b*64 + grp*8)*PIX;
    float s = 0.f, s2 = 0.f;
    for (int i = threadIdx.x; i < 8192; i += 256) {
        float v = in[base + i];
        buf[i] = v; s += v; s2 += v*v;
    }
    block_reduce_2(s, s2, shm);
    float m = s / 8192.f;
    float rs = rsqrtf(s2 / 8192.f - m*m + EPSV);
    for (int i = threadIdx.x; i < 8192; i += 256) {
        int c = grp*8 + (i >> 10);
        out[base + i] = (buf[i] - m) * rs * g[c] + bta[c];
    }
}

// ---------------- conv2: 64->24, 3x3 SAME, + xp; weights in smem ----------------
__global__ void __launch_bounds__(512, 1)
conv2_kernel(const float* __restrict__ y, const float* __restrict__ w,
             const float* __restrict__ xp, float* __restrict__ out) {
    extern __shared__ float s[];         // [IN2] input + [W2SZ] weights
    float* ws = s + IN2;
    int b = blockIdx.x, half = blockIdx.y, tid = threadIdx.x;
    for (int i = tid; i < W2SZ; i += 512) ws[i] = w[i];
    int row0 = half * 16;
    for (int i = tid; i < 64*612; i += 512) {
        int c = i / 612, rem = i % 612, r = rem / 34, cx = rem % 34;
        int gr = row0 + r - 1, gc = cx - 1;
        float v = 0.f;
        if (gr >= 0 && gr < 32 && gc >= 0 && gc < 32)
            v = y[(b*64 + c)*PIX + gr*32 + gc];
        s[c*(18*RS2) + r*RS2 + cx] = v;
    }
    __syncthreads();
    int ocg = tid >> 7;                         // 0..3 -> 6 oc each
    int t = tid & 127;
    int py = t >> 3, px0 = (t & 7) << 2;        // py 0..15
    float acc[6][4];
#pragma unroll
    for (int j = 0; j < 6; j++)
#pragma unroll
        for (int p = 0; p < 4; p++) acc[j][p] = 0.f;
    for (int ic = 0; ic < 64; ic++)
#pragma unroll
        for (int ky = 0; ky < 3; ky++) {
            const float* row = &s[ic*(18*RS2) + (py + ky)*RS2 + px0];
            float r0=row[0],r1=row[1],r2=row[2],r3=row[3],r4=row[4],r5=row[5];
#pragma unroll
            for (int j = 0; j < 6; j++) {
                const float* wq = &ws[((ocg*6 + j)*64 + ic)*9 + ky*3];
                float w0=wq[0], w1=wq[1], w2=wq[2];
                acc[j][0] += r0*w0 + r1*w1 + r2*w2;
                acc[j][1] += r1*w0 + r2*w1 + r3*w2;
                acc[j][2] += r2*w0 + r3*w1 + r4*w2;
                acc[j][3] += r3*w0 + r4*w1 + r5*w2;
            }
        }
    int gy = row0 + py;
#pragma unroll
    for (int j = 0; j < 6; j++)
#pragma unroll
        for (int p = 0; p < 4; p++) {
            int idx = (b*24 + ocg*6 + j)*PIX + gy*32 + px0 + p;
            out[idx] = xp[idx] + acc[j][p];
        }
}

// ---------------- fused gn2 -> +z -> relu -> gn3 ----------------
__global__ void gn23_kernel(const float* __restrict__ t2, const float* __restrict__ z,
                            const float* __restrict__ g2, const float* __restrict__ b2,
                            const float* __restrict__ g3, const float* __restrict__ b3,
                            float* __restrict__ out) {
    __shared__ float buf[3072];
    __shared__ float shm[64];
    int b = blockIdx.x >> 3, grp = blockIdx.x & 7;
    int base = (b*24 + grp*3)*PIX;
    float s = 0.f, s2 = 0.f;
    for (int i = threadIdx.x; i < 3072; i += 256) {
        float v = t2[base + i];
        buf[i] = v; s += v; s2 += v*v;
    }
    block_reduce_2(s, s2, shm);
    float m1 = s / 3072.f;
    float rs1 = rsqrtf(s2 / 3072.f - m1*m1 + EPSV);
    float s3 = 0.f, s4 = 0.f;
    for (int i = threadIdx.x; i < 3072; i += 256) {
        int c = grp*3 + (i >> 10);
        float u = (buf[i] - m1) * rs1 * g2[c] + b2[c];
        float v = fmaxf(z[base + i] + u, 0.f);
        buf[i] = v; s3 += v; s4 += v*v;
    }
    block_reduce_2(s3, s4, shm);
    float m2 = s3 / 3072.f;
    float rs2 = rsqrtf(s4 / 3072.f - m2*m2 + EPSV);
    for (int i = threadIdx.x; i < 3072; i += 256) {
        int c = grp*3 + (i >> 10);
        out[base + i] = (buf[i] - m2) * rs2 * g3[c] + b3[c];
    }
}

// ---------------- Anderson: Gram + fused 6x6 solve per batch ----------------
__global__ void hdot_solve_kernel(int n, const float* __restrict__ Fb,
                                  const float* __restrict__ Xb, float* __restrict__ alpha) {
    int b = blockIdx.x, tid = threadIdx.x;
    float acc[15];
#pragma unroll
    for (int i = 0; i < 15; i++) acc[i] = 0.f;
    size_t bd = (size_t)b * D;
    for (int d = tid; d < D; d += 256) {
        float gg[5];
#pragma unroll
        for (int i = 0; i < 5; i++) {
            size_t off = (size_t)i * (BB*(size_t)D) + bd + d;
            gg[i] = (i < n) ? (Fb[off] - Xb[off]) : 0.f;
        }
        int idx = 0;
#pragma unroll
        for (int i = 0; i < 5; i++)
#pragma unroll
            for (int j = i; j < 5; j++) { acc[idx] += gg[i]*gg[j]; idx++; }
    }
    __shared__ float sh[8][15];
    __shared__ float Hs[15];
    int lane = tid & 31, wid = tid >> 5;
#pragma unroll
    for (int p = 0; p < 15; p++) {
        float v = acc[p];
#pragma unroll
        for (int o = 16; o > 0; o >>= 1) v += __shfl_down_sync(0xffffffffu, v, o);
        if (lane == 0) sh[wid][p] = v;
    }
    __syncthreads();
    if (tid < 15) {
        float v = 0.f;
#pragma unroll
        for (int wq = 0; wq < 8; wq++) v += sh[wq][tid];
        Hs[tid] = v;
    }
    __syncthreads();
    if (tid == 0) {
        // reconstruct symmetric H (upper-tri packed in Hs)
        float Hm[5][5];
        int idx = 0;
        for (int i = 0; i < 5; i++)
            for (int j = i; j < 5; j++) { Hm[i][j] = Hs[idx]; Hm[j][i] = Hs[idx]; idx++; }
        int m = n + 1;
        float A[6][7];
        for (int i = 0; i < m; i++)
            for (int j = 0; j <= m; j++) A[i][j] = 0.f;
        for (int j = 1; j < m; j++) { A[0][j] = 1.f; A[j][0] = 1.f; }
        for (int i = 0; i < n; i++)
            for (int j = 0; j < n; j++)
                A[i+1][j+1] = Hm[i][j] + ((i == j) ? LAMV : 0.f);
        A[0][m] = 1.f;
        for (int col = 0; col < m; col++) {
            int piv = col; float best = fabsf(A[col][col]);
            for (int r = col + 1; r < m; r++) {
                float v = fabsf(A[r][col]);
                if (v > best) { best = v; piv = r; }
            }
            if (piv != col)
                for (int j = col; j <= m; j++) { float t = A[col][j]; A[col][j] = A[piv][j]; A[piv][j] = t; }
            float inv = 1.f / A[col][col];
            for (int r = col + 1; r < m; r++) {
                float f = A[r][col] * inv;
                for (int j = col; j <= m; j++) A[r][j] -= f * A[col][j];
            }
        }
        float xs[6];
        for (int i = m - 1; i >= 0; i--) {
            float v = A[i][m];
            for (int j = i + 1; j < m; j++) v -= A[i][j] * xs[j];
            xs[i] = v / A[i][i];
        }
        for (int i = 0; i < 5; i++) alpha[b*5 + i] = (i < n) ? xs[i + 1] : 0.f;
    }
}

// ---------------- Anderson: xnew = sum alpha_i * F_i (BETA = 1) ----------------
__global__ void xnew_kernel(int n, const float* __restrict__ Fb, const float* __restrict__ alpha,
                            float* __restrict__ Xslot) {
    int idx = blockIdx.x*256 + threadIdx.x;
    if (idx >= BB*D) return;
    int b = idx / D;
    float acc = 0.f;
#pragma unroll
    for (int i = 0; i < 5; i++)
        if (i < n) acc += alpha[b*5 + i] * Fb[(size_t)i * (BB*(size_t)D) + idx];
    Xslot[idx] = acc;
}

// ---------------- post: relu -> BN apply -> 8x8 avgpool ----------------
__global__ void pool_kernel(const float* __restrict__ z, const float* __restrict__ mu,
                            const float* __restrict__ rstd, const float* __restrict__ g,
                            const float* __restrict__ bta, float* __restrict__ pooled) {
    __shared__ float pl[16];
    int b = blockIdx.x / 24, c = blockIdx.x % 24;
    if (threadIdx.x < 16) pl[threadIdx.x] = 0.f;
    __syncthreads();
    float mc = mu[c], rc = rstd[c], gc = g[c], bc = bta[c];
    for (int i = threadIdx.x; i < 1024; i += 256) {
        int yy = i >> 5, xx = i & 31;
        float v = fmaxf(z[(b*24 + c)*PIX + i], 0.f);
        v = (v - mc) * rc * gc + bc;
        atomicAdd(&pl[(yy >> 3)*4 + (xx >> 3)], v);
    }
    __syncthreads();
    if (threadIdx.x < 16)
        pooled[(b*24 + c)*16 + threadIdx.x] = pl[threadIdx.x] * (1.f/64.f);
}

// ---------------- final FC ----------------
__global__ void fc_kernel(const float* __restrict__ pooled, const float* __restrict__ w,
                          const float* __restrict__ bias, float* __restrict__ out) {
    int b = blockIdx.x;
    int warp = threadIdx.x >> 5, lane = threadIdx.x & 31;
    float acc = 0.f;
    for (int k = lane; k < 384; k += 32)
        acc += pooled[b*384 + k] * w[warp*384 + k];
#pragma unroll
    for (int o = 16; o > 0; o >>= 1) acc += __shfl_down_sync(0xffffffffu, acc, o);
    if (lane == 0) out[b*10 + warp] = acc + bias[warp];
}

// ---------------- host orchestration ----------------
extern "C" void kernel_launch(void* const* d_in, const int* in_sizes, int n_in,
                              void* d_out, int out_size) {
    const float* x     = (const float*)d_in[0];
    const float* pw    = (const float*)d_in[1];
    const float* pbia  = (const float*)d_in[2];
    const float* pbn_g = (const float*)d_in[3];
    const float* pbn_b = (const float*)d_in[4];
    const float* w1    = (const float*)d_in[5];
    const float* g1g   = (const float*)d_in[6];
    const float* g1b   = (const float*)d_in[7];
    const float* w2    = (const float*)d_in[8];
    const float* g2g   = (const float*)d_in[9];
    const float* g2b   = (const float*)d_in[10];
    const float* g3g   = (const float*)d_in[11];
    const float* g3b   = (const float*)d_in[12];
    const float* qbn_g = (const float*)d_in[13];
    const float* qbn_b = (const float*)d_in[14];
    const float* fcw   = (const float*)d_in[15];
    const float* fcb   = (const float*)d_in[16];
    float* out = (float*)d_out;

    static bool attr_done = false;
    if (!attr_done) {
        cudaFuncSetAttribute(conv1_kernel, cudaFuncAttributeMaxDynamicSharedMemorySize, SMEM1);
        cudaFuncSetAttribute(conv2_kernel, cudaFuncAttributeMaxDynamicSharedMemorySize, SMEM2);
        attr_done = true;
    }

    float *Xb, *Fb, *xp, *pre, *t1, *yb, *t2, *al, *bmu, *brs, *pmu, *prs, *pl;
    cudaGetSymbolAddress((void**)&Xb,  g_X);
    cudaGetSymbolAddress((void**)&Fb,  g_F);
    cudaGetSymbolAddress((void**)&xp,  g_xp);
    cudaGetSymbolAddress((void**)&pre, g_pre);
    cudaGetSymbolAddress((void**)&t1,  g_t1);
    cudaGetSymbolAddress((void**)&yb,  g_y);
    cudaGetSymbolAddress((void**)&t2,  g_t2);
    cudaGetSymbolAddress((void**)&al,  g_al);
    cudaGetSymbolAddress((void**)&bmu, g_bmu);
    cudaGetSymbolAddress((void**)&brs, g_brs);
    cudaGetSymbolAddress((void**)&pmu, g_pmu);
    cudaGetSymbolAddress((void**)&prs, g_prs);
    cudaGetSymbolAddress((void**)&pl,  g_pool);

    const size_t SLOT = (size_t)BB * D;

    preconv_kernel<<<128, 256>>>(x, pw, pbia, pre);
    bn_stats_kernel<<<24, 512>>>(pre, bmu, brs, 0);
    bn_apply_kernel<<<(BB*D + 255)/256, 256>>>(pre, bmu, brs, pbn_g, pbn_b, xp);

    cudaMemsetAsync(Xb, 0, SLOT * sizeof(float));

    auto runf = [&](const float* z, float* fo) {
        conv1_kernel<<<128, 512, SMEM1>>>(z, w1, t1);
        gn1_kernel<<<1024, 256>>>(t1, g1g, g1b, yb);
        conv2_kernel<<<dim3(128, 2), 512, SMEM2>>>(yb, w2, xp, t2);
        gn23_kernel<<<1024, 256>>>(t2, z, g2g, g2b, g3g, g3b, fo);
    };

    runf(Xb, Fb);                                                 // F0 = f(0)
    cudaMemcpyAsync(Xb + SLOT, Fb, SLOT * sizeof(float), cudaMemcpyDeviceToDevice);
    runf(Xb + SLOT, Fb + SLOT);                                   // F1 = f(F0)

    for (int k = 2; k < 25; k++) {
        int n = (k < 5) ? k : 5;
        int slt = k % 5;
        hdot_solve_kernel<<<128, 256>>>(n, Fb, Xb, al);
        xnew_kernel<<<(BB*D + 255)/256, 256>>>(n, Fb, al, Xb + (size_t)slt * SLOT);
        runf(Xb + (size_t)slt * SLOT, Fb + (size_t)slt * SLOT);
    }

    // z = f(z_star) = F[:,4] (computed by the last iteration)
    const float* zf = Fb + 4 * SLOT;

    bn_stats_kernel<<<24, 512>>>(zf, pmu, prs, 1);
    pool_kernel<<<128*24, 256>>>(zf, pmu, prs, qbn_g, qbn_b, pl);
    fc_kernel<<<128, 320>>>(pl, fcw, fcb, out);
}